// round 13
// baseline (speedup 1.0000x reference)
#include <cuda_runtime.h>
#include <cuda_fp16.h>
#include <math.h>
#include <stdint.h>

#define N       10000
#define NFEAT   512
#define NHID    256
#define NCLASS  40
#define NLAYERS 8
#define MAXW    128
#define WSEG    164
#define NTILES  157

// ---------------- device scratch ----------------
__device__ float g_dinv[N];
__device__ int   g_rowlen[N];
__device__ int   g_cols[(size_t)N * MAXW];
__device__ float g_h[(size_t)N * NHID];
__device__ __align__(16) __half g_x16[(size_t)N * NFEAT];
__device__ __align__(16) __half g_h0_16[(size_t)N * NHID];
__device__ __align__(16) __half g_h16[(size_t)N * NHID];
__device__ __align__(16) __half g_sup16[(size_t)N * NHID];
__device__ __align__(16) __half g_Bimg[(size_t)NLAYERS * NHID * NHID];
__device__ __align__(16) __half g_B0img[(size_t)NFEAT * NHID];

__device__ __forceinline__ uint32_t smem_u32(const void* p) {
    uint32_t a;
    asm("{ .reg .u64 t; cvta.to.shared.u64 t, %1; cvt.u32.u64 %0, t; }" : "=r"(a) : "l"(p));
    return a;
}
__device__ __host__ __forceinline__ uint32_t swz(uint32_t off) {
    return off ^ ((off >> 3) & 0x70);
}

#define CP_ASYNC16(dst, src, sz) \
    asm volatile("cp.async.cg.shared.global [%0], [%1], 16, %2;" \
                 :: "r"(dst), "l"(src), "r"(sz))
#define CP_COMMIT() asm volatile("cp.async.commit_group;")
#define CP_WAIT1()  asm volatile("cp.async.wait_group 1;")

// ==========================================================================
// merged prep
// ==========================================================================
__global__ void prep_all_kernel(const float* __restrict__ x,
                                const float* __restrict__ conv_w,
                                const float* __restrict__ w0) {
    int i = blockIdx.x * 256 + threadIdx.x;
    if (i < N * NFEAT) g_x16[i] = __float2half_rn(x[i]);
    if (i < NLAYERS * NHID * NHID) {
        int n = i & 255, k = (i >> 8) & 255, l = i >> 16;
        int ntile = n >> 6, nl = n & 63, kc = k >> 5, kk = k & 31;
        char* blk = (char*)(g_Bimg + (size_t)l * 65536) + ((size_t)(ntile * 8 + kc)) * 4096;
        *(__half*)(blk + swz(nl * 64 + kk * 2)) = __float2half_rn(conv_w[i]);
    }
    if (i < NFEAT * NHID) {
        int n = i & 255, k = i >> 8;
        int ntile = n >> 6, nl = n & 63, kc = k >> 5, kk = k & 31;
        char* blk = (char*)g_B0img + ((size_t)(ntile * 16 + kc)) * 4096;
        *(__half*)(blk + swz(nl * 64 + kk * 2)) = __float2half_rn(w0[i]);
    }
}

// ==========================================================================
// build_ell v6: depth-4 prefetch + integer-OR early-skip
// ==========================================================================
__device__ __forceinline__ float4 ell_load(const float* row, int chunk, int lane) {
    int c = chunk * 128 + lane * 4;
    float4 v = make_float4(0.f, 0.f, 0.f, 0.f);
    if (c + 3 < N) {
        v = __ldcs((const float4*)(row + c));
    } else {
        if (c + 0 < N) v.x = row[c + 0];
        if (c + 1 < N) v.y = row[c + 1];
        if (c + 2 < N) v.z = row[c + 2];
        if (c + 3 < N) v.w = row[c + 3];
    }
    return v;
}

__global__ __launch_bounds__(256)
void build_ell_kernel(const float* __restrict__ adj) {
    int i = blockIdx.x;
    const float* row = adj + (size_t)i * N;
    int tid = threadIdx.x, lane = tid & 31, w = tid >> 5;
    __shared__ int s_idx[8][WSEG];
    __shared__ int s_cnt[8];
    __shared__ int s_off[8];
    unsigned lt = (1u << lane) - 1u;
    int base = 0;

    #define ELL_PROC(v, chunk) do { \
        uint4 uu = *(uint4*)&(v); \
        unsigned anym = __ballot_sync(0xffffffffu, (uu.x | uu.y | uu.z | uu.w) != 0u); \
        if (anym) { \
            int c = (chunk) * 128 + lane * 4; \
            unsigned b0 = __ballot_sync(0xffffffffu, (v).x != 0.f); \
            unsigned b1 = __ballot_sync(0xffffffffu, (v).y != 0.f); \
            unsigned b2 = __ballot_sync(0xffffffffu, (v).z != 0.f); \
            unsigned b3 = __ballot_sync(0xffffffffu, (v).w != 0.f); \
            int o1 = base + __popc(b0); \
            int o2 = o1 + __popc(b1); \
            int o3 = o2 + __popc(b2); \
            int p; \
            p = base + __popc(b0 & lt); \
            if (((v).x != 0.f) && p < WSEG) s_idx[w][p] = c; \
            p = o1 + __popc(b1 & lt); \
            if (((v).y != 0.f) && p < WSEG) s_idx[w][p] = c + 1; \
            p = o2 + __popc(b2 & lt); \
            if (((v).z != 0.f) && p < WSEG) s_idx[w][p] = c + 2; \
            p = o3 + __popc(b3 & lt); \
            if (((v).w != 0.f) && p < WSEG) s_idx[w][p] = c + 3; \
            base = o3 + __popc(b3); \
        } \
    } while (0)

    float4 buf[4];
    int pc = w;
    #pragma unroll
    for (int d = 0; d < 4; d++) {
        buf[d] = (pc < 79) ? ell_load(row, pc, lane) : make_float4(0.f, 0.f, 0.f, 0.f);
        pc += 8;
    }
    int cur = w;
    for (int it = 0; cur < 79; it++, cur += 8) {
        float4 v = buf[it & 3];
        if (pc < 79) buf[it & 3] = ell_load(row, pc, lane);
        pc += 8;
        ELL_PROC(v, cur);
    }

    if (lane == 0) s_cnt[w] = base < WSEG ? base : WSEG;
    __syncthreads();
    if (tid == 0) {
        int o = 0;
        #pragma unroll
        for (int j = 0; j < 8; j++) { s_off[j] = o; o += s_cnt[j]; }
    }
    __syncthreads();
    int rowoff = i * MAXW;
    int cw = s_cnt[w];
    for (int t = lane; t < cw; t += 32) {
        int pos = s_off[w] + t;
        if (pos < MAXW - 1) g_cols[rowoff + pos] = s_idx[w][t];
    }
    if (tid == 0) {
        int total = s_off[7] + s_cnt[7];
        if (total > MAXW - 1) total = MAXW - 1;
        g_cols[rowoff + total] = i;
        g_rowlen[i] = total + 1;
        g_dinv[i] = rsqrtf((float)(total + 1));
    }
}

// ==========================================================================
// HMMA fp16 GEMM: tile 64x64, BK=64, 128 thr (R11 version, unchanged)
// ==========================================================================
__global__ __launch_bounds__(128, 6)
void gemm_hmma_kernel(const __half* __restrict__ A, int M, int K,
                      const __half* __restrict__ Bimg,
                      float* __restrict__ C,
                      __half* __restrict__ C16,
                      const float* __restrict__ bias,
                      const __half* __restrict__ resid16,
                      float theta, float rtheta, int mode) {
    __shared__ __align__(128) __half sA[2][64 * 64];
    __shared__ __align__(128) __half sB[2][64 * 64];
    int tid = threadIdx.x, lane = tid & 31, wid = tid >> 5;
    int wm = wid & 1, wn = wid >> 1;
    int bm = blockIdx.x * 64;
    int nc0 = blockIdx.y * 64;
    const __half* Bsrc = Bimg + (size_t)blockIdx.y * (K >> 5) * 2048;
    int nch = K >> 6;

    uint32_t sAb = smem_u32(sA), sBb = smem_u32(sB);

    float acc[2][4][4];
    #pragma unroll
    for (int i = 0; i < 2; i++)
        #pragma unroll
        for (int j = 0; j < 4; j++)
            #pragma unroll
            for (int r = 0; r < 4; r++) acc[i][j][r] = 0.f;

    int rowA = wm * 32 + (lane & 15);
    int colA = (lane >> 4) * 16;
    int rowB = wn * 32 + (lane & 7) + ((lane & 16) ? 8 : 0);
    int colB = ((lane >> 3) & 1) * 16;

    #define GSTAGE(c, buf) do { \
        int _c = (c), _b = (buf); \
        for (int t = tid; t < 512; t += 128) { \
            int row = t >> 3, j = t & 7; \
            uint32_t dst = sAb + _b * 8192 + swz(row * 128 + j * 16); \
            int gr = bm + row; \
            const __half* src = A + (size_t)(gr < M ? gr : 0) * K + _c * 64 + j * 8; \
            CP_ASYNC16(dst, src, (gr < M) ? 16 : 0); \
        } \
        for (int t = tid; t < 512; t += 128) { \
            uint32_t dst = sBb + _b * 8192 + t * 16; \
            const __half* src = Bsrc + (size_t)_c * 4096 + t * 8; \
            CP_ASYNC16(dst, src, 16); \
        } \
    } while (0)

    GSTAGE(0, 0);
    CP_COMMIT();

    for (int c = 0; c < nch; c++) {
        if (c + 1 < nch) GSTAGE(c + 1, (c + 1) & 1);
        CP_COMMIT();
        CP_WAIT1();
        __syncthreads();

        uint32_t aB = sAb + (c & 1) * 8192;
        uint32_t bB = sBb + (c & 1) * 8192;
        #pragma unroll
        for (int s = 0; s < 4; s++) {
            uint32_t a[2][4];
            uint32_t b[4][2];
            #pragma unroll
            for (int mm = 0; mm < 2; mm++) {
                uint32_t addr = aB + swz((rowA + mm * 16) * 128 + s * 32 + colA);
                asm volatile("ldmatrix.sync.aligned.m8n8.x4.shared.b16 {%0,%1,%2,%3}, [%4];"
                    : "=r"(a[mm][0]), "=r"(a[mm][1]), "=r"(a[mm][2]), "=r"(a[mm][3])
                    : "r"(addr));
            }
            #pragma unroll
            for (int p = 0; p < 2; p++) {
                uint32_t addr = bB + (s >> 1) * 4096
                              + swz((rowB + p * 16) * 64 + (s & 1) * 32 + colB);
                asm volatile("ldmatrix.sync.aligned.m8n8.x4.shared.b16 {%0,%1,%2,%3}, [%4];"
                    : "=r"(b[2 * p][0]), "=r"(b[2 * p][1]),
                      "=r"(b[2 * p + 1][0]), "=r"(b[2 * p + 1][1])
                    : "r"(addr));
            }
            #pragma unroll
            for (int mm = 0; mm < 2; mm++)
                #pragma unroll
                for (int nf = 0; nf < 4; nf++)
                    asm volatile(
                        "mma.sync.aligned.m16n8k16.row.col.f32.f16.f16.f32 "
                        "{%0,%1,%2,%3}, {%4,%5,%6,%7}, {%8,%9}, {%0,%1,%2,%3};"
                        : "+f"(acc[mm][nf][0]), "+f"(acc[mm][nf][1]),
                          "+f"(acc[mm][nf][2]), "+f"(acc[mm][nf][3])
                        : "r"(a[mm][0]), "r"(a[mm][1]), "r"(a[mm][2]), "r"(a[mm][3]),
                          "r"(b[nf][0]), "r"(b[nf][1]));
        }
        __syncthreads();
    }

    int quad = lane >> 2, tq = lane & 3;
    #pragma unroll
    for (int mm = 0; mm < 2; mm++) {
        #pragma unroll
        for (int half = 0; half < 2; half++) {
            int grow = bm + wm * 32 + mm * 16 + quad + half * 8;
            if (grow >= M) continue;
            #pragma unroll
            for (int nf = 0; nf < 4; nf++) {
                int nc = nc0 + wn * 32 + nf * 8 + tq * 2;
                float v0 = acc[mm][nf][half * 2 + 0];
                float v1 = acc[mm][nf][half * 2 + 1];
                float o0, o1;
                if (mode == 0) {
                    o0 = fmaxf(v0 + bias[nc], 0.f);
                    o1 = fmaxf(v1 + bias[nc + 1], 0.f);
                } else {
                    float2 r = __half22float2(
                        *(const __half2*)(resid16 + (size_t)grow * NHID + nc));
                    o0 = fmaxf(theta * v0 + rtheta * r.x, 0.f);
                    o1 = fmaxf(theta * v1 + rtheta * r.y, 0.f);
                }
                if (C) *(float2*)(C + (size_t)grow * NHID + nc) = make_float2(o0, o1);
                *(__half2*)(C16 + (size_t)grow * NHID + nc) = __floats2half2_rn(o0, o1);
            }
        }
    }
}

// ==========================================================================
// SpMM v8: v7 structure (2 rows/block, 256 thr, 2-way split-K per row),
// packed-f32x2 FMA inner loop: LDS.128 (w,w,cbits) + LDG.64 + 4 cvt + 2 FFMA2.
// Bit-identical fp32 numerics, ~18% fewer issue slots.
// ==========================================================================
__global__ __launch_bounds__(256)
void spmm_support_kernel(const uint2* __restrict__ hv,
                         const uint2* __restrict__ h0v,
                         uint2* __restrict__ supv) {
    int tid = threadIdx.x;
    int rl = tid >> 7;
    int t = tid & 127;
    int i = blockIdx.x * 2 + rl;
    __shared__ __align__(16) float4 s_cw[2][MAXW];   // (w, w, int_bits(c*64), 0)
    __shared__ float s_part[2][64][4];
    int len = g_rowlen[i];
    if (t < len) {
        int c = g_cols[i * MAXW + t];
        float wv = g_dinv[c];
        s_cw[rl][t] = make_float4(wv, wv, __int_as_float(c * 64), 0.f);
    }
    __syncthreads();
    int g = t & 63, hlf = t >> 6;
    int lhalf = (len + 1) >> 1;
    int k0 = hlf ? lhalf : 0;
    int k1 = hlf ? len : lhalf;

    unsigned long long acc01 = 0ull, acc23 = 0ull;   // packed (f32,f32) pairs
    #pragma unroll 4
    for (int k = k0; k < k1; k++) {
        float4 cw = s_cw[rl][k];
        unsigned long long w2;
        asm("mov.b64 %0, {%1,%2};" : "=l"(w2) : "f"(cw.x), "f"(cw.y));
        uint2 u = __ldg(&hv[__float_as_int(cw.z) + g]);
        float2 f0 = __half22float2(*(__half2*)&u.x);
        float2 f1 = __half22float2(*(__half2*)&u.y);
        unsigned long long p0, p1;
        asm("mov.b64 %0, {%1,%2};" : "=l"(p0) : "f"(f0.x), "f"(f0.y));
        asm("mov.b64 %0, {%1,%2};" : "=l"(p1) : "f"(f1.x), "f"(f1.y));
        asm("fma.rn.f32x2 %0, %1, %2, %0;" : "+l"(acc01) : "l"(p0), "l"(w2));
        asm("fma.rn.f32x2 %0, %1, %2, %0;" : "+l"(acc23) : "l"(p1), "l"(w2));
    }
    float a0, a1, a2, a3;
    asm("mov.b64 {%0,%1}, %2;" : "=f"(a0), "=f"(a1) : "l"(acc01));
    asm("mov.b64 {%0,%1}, %2;" : "=f"(a2), "=f"(a3) : "l"(acc23));

    if (hlf) {
        s_part[rl][g][0] = a0; s_part[rl][g][1] = a1;
        s_part[rl][g][2] = a2; s_part[rl][g][3] = a3;
    }
    __syncthreads();
    if (!hlf) {
        a0 += s_part[rl][g][0]; a1 += s_part[rl][g][1];
        a2 += s_part[rl][g][2]; a3 += s_part[rl][g][3];
        float di = 0.9f * g_dinv[i];
        uint2 r = __ldg(&h0v[i * 64 + g]);
        float2 r0 = __half22float2(*(__half2*)&r.x);
        float2 r1 = __half22float2(*(__half2*)&r.y);
        float o0 = di * a0 + 0.1f * r0.x;
        float o1 = di * a1 + 0.1f * r0.y;
        float o2 = di * a2 + 0.1f * r1.x;
        float o3 = di * a3 + 0.1f * r1.y;
        __half2 q0 = __floats2half2_rn(o0, o1);
        __half2 q1 = __floats2half2_rn(o2, o3);
        uint2 wv2;
        wv2.x = *(unsigned*)&q0;
        wv2.y = *(unsigned*)&q1;
        supv[i * 64 + g] = wv2;
    }
}

// ==========================================================================
// head (unchanged)
// ==========================================================================
#define HPAD 260
#define HROWS 64
__global__ __launch_bounds__(128)
void head_kernel(const float* __restrict__ h,
                 const float* __restrict__ w1,
                 const float* __restrict__ b1,
                 float* __restrict__ out) {
    extern __shared__ float sm[];
    float* w1t = sm;
    float* hs  = sm + NCLASS * HPAD;
    float* slog = hs + HROWS * HPAD;

    int tid = threadIdx.x;
    int row0 = blockIdx.x * HROWS;

    for (int t = tid; t < NHID * NCLASS; t += 128) {
        int k = t / NCLASS, c = t % NCLASS;
        w1t[c * HPAD + k] = w1[t];
    }
    for (int t = tid; t < HROWS * NHID; t += 128) {
        int r = t >> 8, k = t & 255;
        int gr = row0 + r;
        hs[r * HPAD + k] = (gr < N) ? h[(size_t)gr * NHID + k] : 0.f;
    }
    __syncthreads();

    int cg = tid & 7;
    int rg = tid >> 3;
    float acc[4][5];
    #pragma unroll
    for (int mm = 0; mm < 4; mm++)
        #pragma unroll
        for (int j = 0; j < 5; j++) acc[mm][j] = 0.f;

    for (int k0 = 0; k0 < NHID; k0 += 4) {
        float4 wv[5];
        #pragma unroll
        for (int j = 0; j < 5; j++)
            wv[j] = *(const float4*)&w1t[(cg * 5 + j) * HPAD + k0];
        #pragma unroll
        for (int mm = 0; mm < 4; mm++) {
            float4 hvv = *(const float4*)&hs[(rg * 4 + mm) * HPAD + k0];
            #pragma unroll
            for (int j = 0; j < 5; j++)
                acc[mm][j] += hvv.x * wv[j].x + hvv.y * wv[j].y
                            + hvv.z * wv[j].z + hvv.w * wv[j].w;
        }
    }
    #pragma unroll
    for (int mm = 0; mm < 4; mm++)
        #pragma unroll
        for (int j = 0; j < 5; j++)
            slog[(rg * 4 + mm) * NCLASS + cg * 5 + j] = acc[mm][j] + b1[cg * 5 + j];
    __syncthreads();

    if (tid < HROWS) {
        int gr = row0 + tid;
        if (gr < N) {
            const float* l = slog + tid * NCLASS;
            float m = -1e30f;
            #pragma unroll 8
            for (int c = 0; c < NCLASS; c++) m = fmaxf(m, l[c]);
            float s = 0.f;
            #pragma unroll 8
            for (int c = 0; c < NCLASS; c++) s += expf(l[c] - m);
            float nrm = m + logf(s);
            float* o = out + (size_t)gr * NCLASS;
            #pragma unroll 8
            for (int c = 0; c < NCLASS; c++) o[c] = l[c] - nrm;
        }
    }
}

// ==========================================================================
// host driver — stream fork: build_ell || (prep + h0 GEMM); layers serial
// ==========================================================================
extern "C" void kernel_launch(void* const* d_in, const int* in_sizes, int n_in,
                              void* d_out, int out_size) {
    const float* x      = (const float*)d_in[0];
    const float* adj    = (const float*)d_in[1];
    const float* w0     = (const float*)d_in[2];
    const float* b0     = (const float*)d_in[3];
    const float* conv_w = (const float*)d_in[4];
    const float* w1     = (const float*)d_in[5];
    const float* b1     = (const float*)d_in[6];
    float* out = (float*)d_out;

    float *p_h;
    __half *p_Bimg, *p_B0img, *p_x16, *p_h016, *p_h16, *p_sup16;
    cudaGetSymbolAddress((void**)&p_h, g_h);
    cudaGetSymbolAddress((void**)&p_Bimg, g_Bimg);
    cudaGetSymbolAddress((void**)&p_B0img, g_B0img);
    cudaGetSymbolAddress((void**)&p_x16, g_x16);
    cudaGetSymbolAddress((void**)&p_h016, g_h0_16);
    cudaGetSymbolAddress((void**)&p_h16, g_h16);
    cudaGetSymbolAddress((void**)&p_sup16, g_sup16);

    static cudaStream_t s1 = nullptr;
    static cudaEvent_t evFork = nullptr, evJoin = nullptr;
    static int head_smem = 0;
    if (!s1) {
        cudaStreamCreate(&s1);
        cudaEventCreateWithFlags(&evFork, cudaEventDisableTiming);
        cudaEventCreateWithFlags(&evJoin, cudaEventDisableTiming);
        head_smem = (NCLASS * HPAD + HROWS * HPAD + HROWS * NCLASS) * 4;
        cudaFuncSetAttribute(head_kernel, cudaFuncAttributeMaxDynamicSharedMemorySize, head_smem);
    }

    cudaEventRecord(evFork, 0);
    cudaStreamWaitEvent(s1, evFork, 0);
    build_ell_kernel<<<N, 256, 0, s1>>>(adj);
    cudaEventRecord(evJoin, s1);

    prep_all_kernel<<<(N * NFEAT + 255) / 256, 256>>>(x, conv_w, w0);

    dim3 gg(NTILES, 4);
    gemm_hmma_kernel<<<gg, 128>>>(p_x16, N, NFEAT, p_B0img, nullptr, p_h016,
                                  b0, nullptr, 0.f, 0.f, 0);

    cudaStreamWaitEvent(0, evJoin, 0);

    const __half* hcur = p_h016;
    for (int l = 0; l < NLAYERS; l++) {
        float theta = logf(0.5f / (float)(l + 1) + 1.0f);
        float rtheta = 1.0f - theta;
        spmm_support_kernel<<<N / 2, 256>>>((const uint2*)hcur, (const uint2*)p_h016,
                                            (uint2*)p_sup16);
        float* cdst = (l == NLAYERS - 1) ? p_h : nullptr;
        gemm_hmma_kernel<<<gg, 128>>>(p_sup16, N, NHID,
                                      p_Bimg + (size_t)l * 65536, cdst, p_h16,
                                      nullptr, p_sup16, theta, rtheta, 1);
        hcur = p_h16;
    }

    head_kernel<<<(N + HROWS - 1) / HROWS, 128, head_smem>>>(p_h, w1, b1, out);
}

// round 14
// speedup vs baseline: 1.0572x; 1.0572x over previous
#include <cuda_runtime.h>
#include <cuda_fp16.h>
#include <math.h>
#include <stdint.h>

#define N       10000
#define NFEAT   512
#define NHID    256
#define NCLASS  40
#define NLAYERS 8
#define MAXW    128
#define WSEG    164
#define NTILES  157

// ---------------- device scratch ----------------
__device__ float g_dinv[N];
__device__ int   g_rowlen[N];
__device__ int   g_cols[(size_t)N * MAXW];
__device__ float g_h[(size_t)N * NHID];
__device__ __align__(16) __half g_x16[(size_t)N * NFEAT];
__device__ __align__(16) __half g_h0_16[(size_t)N * NHID];
__device__ __align__(16) __half g_h16[(size_t)N * NHID];
__device__ __align__(16) __half g_sup16[(size_t)N * NHID];
__device__ __align__(16) __half g_Bimg[(size_t)NLAYERS * NHID * NHID];
__device__ __align__(16) __half g_B0img[(size_t)NFEAT * NHID];

__device__ __forceinline__ uint32_t smem_u32(const void* p) {
    uint32_t a;
    asm("{ .reg .u64 t; cvta.to.shared.u64 t, %1; cvt.u32.u64 %0, t; }" : "=r"(a) : "l"(p));
    return a;
}
__device__ __host__ __forceinline__ uint32_t swz(uint32_t off) {
    return off ^ ((off >> 3) & 0x70);
}

#define CP_ASYNC16(dst, src, sz) \
    asm volatile("cp.async.cg.shared.global [%0], [%1], 16, %2;" \
                 :: "r"(dst), "l"(src), "r"(sz))
#define CP_COMMIT() asm volatile("cp.async.commit_group;")
#define CP_WAIT1()  asm volatile("cp.async.wait_group 1;")

// ==========================================================================
// merged prep
// ==========================================================================
__global__ void prep_all_kernel(const float* __restrict__ x,
                                const float* __restrict__ conv_w,
                                const float* __restrict__ w0) {
    int i = blockIdx.x * 256 + threadIdx.x;
    if (i < N * NFEAT) g_x16[i] = __float2half_rn(x[i]);
    if (i < NLAYERS * NHID * NHID) {
        int n = i & 255, k = (i >> 8) & 255, l = i >> 16;
        int ntile = n >> 6, nl = n & 63, kc = k >> 5, kk = k & 31;
        char* blk = (char*)(g_Bimg + (size_t)l * 65536) + ((size_t)(ntile * 8 + kc)) * 4096;
        *(__half*)(blk + swz(nl * 64 + kk * 2)) = __float2half_rn(conv_w[i]);
    }
    if (i < NFEAT * NHID) {
        int n = i & 255, k = i >> 8;
        int ntile = n >> 6, nl = n & 63, kc = k >> 5, kk = k & 31;
        char* blk = (char*)g_B0img + ((size_t)(ntile * 16 + kc)) * 4096;
        *(__half*)(blk + swz(nl * 64 + kk * 2)) = __float2half_rn(w0[i]);
    }
}

// ==========================================================================
// build_ell v6: depth-4 prefetch + integer-OR early-skip
// ==========================================================================
__device__ __forceinline__ float4 ell_load(const float* row, int chunk, int lane) {
    int c = chunk * 128 + lane * 4;
    float4 v = make_float4(0.f, 0.f, 0.f, 0.f);
    if (c + 3 < N) {
        v = __ldcs((const float4*)(row + c));
    } else {
        if (c + 0 < N) v.x = row[c + 0];
        if (c + 1 < N) v.y = row[c + 1];
        if (c + 2 < N) v.z = row[c + 2];
        if (c + 3 < N) v.w = row[c + 3];
    }
    return v;
}

__global__ __launch_bounds__(256)
void build_ell_kernel(const float* __restrict__ adj) {
    int i = blockIdx.x;
    const float* row = adj + (size_t)i * N;
    int tid = threadIdx.x, lane = tid & 31, w = tid >> 5;
    __shared__ int s_idx[8][WSEG];
    __shared__ int s_cnt[8];
    __shared__ int s_off[8];
    unsigned lt = (1u << lane) - 1u;
    int base = 0;

    #define ELL_PROC(v, chunk) do { \
        uint4 uu = *(uint4*)&(v); \
        unsigned anym = __ballot_sync(0xffffffffu, (uu.x | uu.y | uu.z | uu.w) != 0u); \
        if (anym) { \
            int c = (chunk) * 128 + lane * 4; \
            unsigned b0 = __ballot_sync(0xffffffffu, (v).x != 0.f); \
            unsigned b1 = __ballot_sync(0xffffffffu, (v).y != 0.f); \
            unsigned b2 = __ballot_sync(0xffffffffu, (v).z != 0.f); \
            unsigned b3 = __ballot_sync(0xffffffffu, (v).w != 0.f); \
            int o1 = base + __popc(b0); \
            int o2 = o1 + __popc(b1); \
            int o3 = o2 + __popc(b2); \
            int p; \
            p = base + __popc(b0 & lt); \
            if (((v).x != 0.f) && p < WSEG) s_idx[w][p] = c; \
            p = o1 + __popc(b1 & lt); \
            if (((v).y != 0.f) && p < WSEG) s_idx[w][p] = c + 1; \
            p = o2 + __popc(b2 & lt); \
            if (((v).z != 0.f) && p < WSEG) s_idx[w][p] = c + 2; \
            p = o3 + __popc(b3 & lt); \
            if (((v).w != 0.f) && p < WSEG) s_idx[w][p] = c + 3; \
            base = o3 + __popc(b3); \
        } \
    } while (0)

    float4 buf[4];
    int pc = w;
    #pragma unroll
    for (int d = 0; d < 4; d++) {
        buf[d] = (pc < 79) ? ell_load(row, pc, lane) : make_float4(0.f, 0.f, 0.f, 0.f);
        pc += 8;
    }
    int cur = w;
    for (int it = 0; cur < 79; it++, cur += 8) {
        float4 v = buf[it & 3];
        if (pc < 79) buf[it & 3] = ell_load(row, pc, lane);
        pc += 8;
        ELL_PROC(v, cur);
    }

    if (lane == 0) s_cnt[w] = base < WSEG ? base : WSEG;
    __syncthreads();
    if (tid == 0) {
        int o = 0;
        #pragma unroll
        for (int j = 0; j < 8; j++) { s_off[j] = o; o += s_cnt[j]; }
    }
    __syncthreads();
    int rowoff = i * MAXW;
    int cw = s_cnt[w];
    for (int t = lane; t < cw; t += 32) {
        int pos = s_off[w] + t;
        if (pos < MAXW - 1) g_cols[rowoff + pos] = s_idx[w][t];
    }
    if (tid == 0) {
        int total = s_off[7] + s_cnt[7];
        if (total > MAXW - 1) total = MAXW - 1;
        g_cols[rowoff + total] = i;
        g_rowlen[i] = total + 1;
        g_dinv[i] = rsqrtf((float)(total + 1));
    }
}

// ==========================================================================
// HMMA fp16 GEMM: tile 64x64, BK=64, 128 thr; C and C16 both optional
// ==========================================================================
__global__ __launch_bounds__(128, 6)
void gemm_hmma_kernel(const __half* __restrict__ A, int M, int K,
                      const __half* __restrict__ Bimg,
                      float* __restrict__ C,
                      __half* __restrict__ C16,
                      const float* __restrict__ bias,
                      const __half* __restrict__ resid16,
                      float theta, float rtheta, int mode) {
    __shared__ __align__(128) __half sA[2][64 * 64];
    __shared__ __align__(128) __half sB[2][64 * 64];
    int tid = threadIdx.x, lane = tid & 31, wid = tid >> 5;
    int wm = wid & 1, wn = wid >> 1;
    int bm = blockIdx.x * 64;
    int nc0 = blockIdx.y * 64;
    const __half* Bsrc = Bimg + (size_t)blockIdx.y * (K >> 5) * 2048;
    int nch = K >> 6;

    uint32_t sAb = smem_u32(sA), sBb = smem_u32(sB);

    float acc[2][4][4];
    #pragma unroll
    for (int i = 0; i < 2; i++)
        #pragma unroll
        for (int j = 0; j < 4; j++)
            #pragma unroll
            for (int r = 0; r < 4; r++) acc[i][j][r] = 0.f;

    int rowA = wm * 32 + (lane & 15);
    int colA = (lane >> 4) * 16;
    int rowB = wn * 32 + (lane & 7) + ((lane & 16) ? 8 : 0);
    int colB = ((lane >> 3) & 1) * 16;

    #define GSTAGE(c, buf) do { \
        int _c = (c), _b = (buf); \
        for (int t = tid; t < 512; t += 128) { \
            int row = t >> 3, j = t & 7; \
            uint32_t dst = sAb + _b * 8192 + swz(row * 128 + j * 16); \
            int gr = bm + row; \
            const __half* src = A + (size_t)(gr < M ? gr : 0) * K + _c * 64 + j * 8; \
            CP_ASYNC16(dst, src, (gr < M) ? 16 : 0); \
        } \
        for (int t = tid; t < 512; t += 128) { \
            uint32_t dst = sBb + _b * 8192 + t * 16; \
            const __half* src = Bsrc + (size_t)_c * 4096 + t * 8; \
            CP_ASYNC16(dst, src, 16); \
        } \
    } while (0)

    GSTAGE(0, 0);
    CP_COMMIT();

    for (int c = 0; c < nch; c++) {
        if (c + 1 < nch) GSTAGE(c + 1, (c + 1) & 1);
        CP_COMMIT();
        CP_WAIT1();
        __syncthreads();

        uint32_t aB = sAb + (c & 1) * 8192;
        uint32_t bB = sBb + (c & 1) * 8192;
        #pragma unroll
        for (int s = 0; s < 4; s++) {
            uint32_t a[2][4];
            uint32_t b[4][2];
            #pragma unroll
            for (int mm = 0; mm < 2; mm++) {
                uint32_t addr = aB + swz((rowA + mm * 16) * 128 + s * 32 + colA);
                asm volatile("ldmatrix.sync.aligned.m8n8.x4.shared.b16 {%0,%1,%2,%3}, [%4];"
                    : "=r"(a[mm][0]), "=r"(a[mm][1]), "=r"(a[mm][2]), "=r"(a[mm][3])
                    : "r"(addr));
            }
            #pragma unroll
            for (int p = 0; p < 2; p++) {
                uint32_t addr = bB + (s >> 1) * 4096
                              + swz((rowB + p * 16) * 64 + (s & 1) * 32 + colB);
                asm volatile("ldmatrix.sync.aligned.m8n8.x4.shared.b16 {%0,%1,%2,%3}, [%4];"
                    : "=r"(b[2 * p][0]), "=r"(b[2 * p][1]),
                      "=r"(b[2 * p + 1][0]), "=r"(b[2 * p + 1][1])
                    : "r"(addr));
            }
            #pragma unroll
            for (int mm = 0; mm < 2; mm++)
                #pragma unroll
                for (int nf = 0; nf < 4; nf++)
                    asm volatile(
                        "mma.sync.aligned.m16n8k16.row.col.f32.f16.f16.f32 "
                        "{%0,%1,%2,%3}, {%4,%5,%6,%7}, {%8,%9}, {%0,%1,%2,%3};"
                        : "+f"(acc[mm][nf][0]), "+f"(acc[mm][nf][1]),
                          "+f"(acc[mm][nf][2]), "+f"(acc[mm][nf][3])
                        : "r"(a[mm][0]), "r"(a[mm][1]), "r"(a[mm][2]), "r"(a[mm][3]),
                          "r"(b[nf][0]), "r"(b[nf][1]));
        }
        __syncthreads();
    }

    int quad = lane >> 2, tq = lane & 3;
    #pragma unroll
    for (int mm = 0; mm < 2; mm++) {
        #pragma unroll
        for (int half = 0; half < 2; half++) {
            int grow = bm + wm * 32 + mm * 16 + quad + half * 8;
            if (grow >= M) continue;
            #pragma unroll
            for (int nf = 0; nf < 4; nf++) {
                int nc = nc0 + wn * 32 + nf * 8 + tq * 2;
                float v0 = acc[mm][nf][half * 2 + 0];
                float v1 = acc[mm][nf][half * 2 + 1];
                float o0, o1;
                if (mode == 0) {
                    o0 = fmaxf(v0 + bias[nc], 0.f);
                    o1 = fmaxf(v1 + bias[nc + 1], 0.f);
                } else {
                    float2 r = __half22float2(
                        *(const __half2*)(resid16 + (size_t)grow * NHID + nc));
                    o0 = fmaxf(theta * v0 + rtheta * r.x, 0.f);
                    o1 = fmaxf(theta * v1 + rtheta * r.y, 0.f);
                }
                if (C) *(float2*)(C + (size_t)grow * NHID + nc) = make_float2(o0, o1);
                if (C16)
                    *(__half2*)(C16 + (size_t)grow * NHID + nc) = __floats2half2_rn(o0, o1);
            }
        }
    }
}

// ==========================================================================
// SpMM v7 (R11): 2 rows/block, 256 thr, 2-way split-K, packed (w,c) float2
// ==========================================================================
__global__ __launch_bounds__(256)
void spmm_support_kernel(const uint2* __restrict__ hv,
                         const uint2* __restrict__ h0v,
                         uint2* __restrict__ supv) {
    int tid = threadIdx.x;
    int rl = tid >> 7;
    int t = tid & 127;
    int i = blockIdx.x * 2 + rl;
    __shared__ float2 s_cw[2][MAXW];
    __shared__ float s_part[2][64][4];
    int len = g_rowlen[i];
    if (t < len) {
        int c = g_cols[i * MAXW + t];
        s_cw[rl][t] = make_float2(g_dinv[c], __int_as_float(c * 64));
    }
    __syncthreads();
    int g = t & 63, hlf = t >> 6;
    int lhalf = (len + 1) >> 1;
    int k0 = hlf ? lhalf : 0;
    int k1 = hlf ? len : lhalf;
    float a0 = 0.f, a1 = 0.f, a2 = 0.f, a3 = 0.f;
    #pragma unroll 4
    for (int k = k0; k < k1; k++) {
        float2 cw = s_cw[rl][k];
        uint2 u = __ldg(&hv[__float_as_int(cw.y) + g]);
        float2 f0 = __half22float2(*(__half2*)&u.x);
        float2 f1 = __half22float2(*(__half2*)&u.y);
        a0 += cw.x * f0.x; a1 += cw.x * f0.y;
        a2 += cw.x * f1.x; a3 += cw.x * f1.y;
    }
    if (hlf) {
        s_part[rl][g][0] = a0; s_part[rl][g][1] = a1;
        s_part[rl][g][2] = a2; s_part[rl][g][3] = a3;
    }
    __syncthreads();
    if (!hlf) {
        a0 += s_part[rl][g][0]; a1 += s_part[rl][g][1];
        a2 += s_part[rl][g][2]; a3 += s_part[rl][g][3];
        float di = 0.9f * g_dinv[i];
        uint2 r = __ldg(&h0v[i * 64 + g]);
        float2 r0 = __half22float2(*(__half2*)&r.x);
        float2 r1 = __half22float2(*(__half2*)&r.y);
        float o0 = di * a0 + 0.1f * r0.x;
        float o1 = di * a1 + 0.1f * r0.y;
        float o2 = di * a2 + 0.1f * r1.x;
        float o3 = di * a3 + 0.1f * r1.y;
        __half2 q0 = __floats2half2_rn(o0, o1);
        __half2 q1 = __floats2half2_rn(o2, o3);
        uint2 wv2;
        wv2.x = *(unsigned*)&q0;
        wv2.y = *(unsigned*)&q1;
        supv[i * 64 + g] = wv2;
    }
}

// ==========================================================================
// head (unchanged)
// ==========================================================================
#define HPAD 260
#define HROWS 64
__global__ __launch_bounds__(128)
void head_kernel(const float* __restrict__ h,
                 const float* __restrict__ w1,
                 const float* __restrict__ b1,
                 float* __restrict__ out) {
    extern __shared__ float sm[];
    float* w1t = sm;
    float* hs  = sm + NCLASS * HPAD;
    float* slog = hs + HROWS * HPAD;

    int tid = threadIdx.x;
    int row0 = blockIdx.x * HROWS;

    for (int t = tid; t < NHID * NCLASS; t += 128) {
        int k = t / NCLASS, c = t % NCLASS;
        w1t[c * HPAD + k] = w1[t];
    }
    for (int t = tid; t < HROWS * NHID; t += 128) {
        int r = t >> 8, k = t & 255;
        int gr = row0 + r;
        hs[r * HPAD + k] = (gr < N) ? h[(size_t)gr * NHID + k] : 0.f;
    }
    __syncthreads();

    int cg = tid & 7;
    int rg = tid >> 3;
    float acc[4][5];
    #pragma unroll
    for (int mm = 0; mm < 4; mm++)
        #pragma unroll
        for (int j = 0; j < 5; j++) acc[mm][j] = 0.f;

    for (int k0 = 0; k0 < NHID; k0 += 4) {
        float4 wv[5];
        #pragma unroll
        for (int j = 0; j < 5; j++)
            wv[j] = *(const float4*)&w1t[(cg * 5 + j) * HPAD + k0];
        #pragma unroll
        for (int mm = 0; mm < 4; mm++) {
            float4 hvv = *(const float4*)&hs[(rg * 4 + mm) * HPAD + k0];
            #pragma unroll
            for (int j = 0; j < 5; j++)
                acc[mm][j] += hvv.x * wv[j].x + hvv.y * wv[j].y
                            + hvv.z * wv[j].z + hvv.w * wv[j].w;
        }
    }
    #pragma unroll
    for (int mm = 0; mm < 4; mm++)
        #pragma unroll
        for (int j = 0; j < 5; j++)
            slog[(rg * 4 + mm) * NCLASS + cg * 5 + j] = acc[mm][j] + b1[cg * 5 + j];
    __syncthreads();

    if (tid < HROWS) {
        int gr = row0 + tid;
        if (gr < N) {
            const float* l = slog + tid * NCLASS;
            float m = -1e30f;
            #pragma unroll 8
            for (int c = 0; c < NCLASS; c++) m = fmaxf(m, l[c]);
            float s = 0.f;
            #pragma unroll 8
            for (int c = 0; c < NCLASS; c++) s += expf(l[c] - m);
            float nrm = m + logf(s);
            float* o = out + (size_t)gr * NCLASS;
            #pragma unroll 8
            for (int c = 0; c < NCLASS; c++) o[c] = l[c] - nrm;
        }
    }
}

// ==========================================================================
// host driver — stream fork: build_ell || (prep + h0 GEMM); layers serial
// ==========================================================================
extern "C" void kernel_launch(void* const* d_in, const int* in_sizes, int n_in,
                              void* d_out, int out_size) {
    const float* x      = (const float*)d_in[0];
    const float* adj    = (const float*)d_in[1];
    const float* w0     = (const float*)d_in[2];
    const float* b0     = (const float*)d_in[3];
    const float* conv_w = (const float*)d_in[4];
    const float* w1     = (const float*)d_in[5];
    const float* b1     = (const float*)d_in[6];
    float* out = (float*)d_out;

    float *p_h;
    __half *p_Bimg, *p_B0img, *p_x16, *p_h016, *p_h16, *p_sup16;
    cudaGetSymbolAddress((void**)&p_h, g_h);
    cudaGetSymbolAddress((void**)&p_Bimg, g_Bimg);
    cudaGetSymbolAddress((void**)&p_B0img, g_B0img);
    cudaGetSymbolAddress((void**)&p_x16, g_x16);
    cudaGetSymbolAddress((void**)&p_h016, g_h0_16);
    cudaGetSymbolAddress((void**)&p_h16, g_h16);
    cudaGetSymbolAddress((void**)&p_sup16, g_sup16);

    static cudaStream_t s1 = nullptr;
    static cudaEvent_t evFork = nullptr, evJoin = nullptr;
    static int head_smem = 0;
    if (!s1) {
        cudaStreamCreate(&s1);
        cudaEventCreateWithFlags(&evFork, cudaEventDisableTiming);
        cudaEventCreateWithFlags(&evJoin, cudaEventDisableTiming);
        head_smem = (NCLASS * HPAD + HROWS * HPAD + HROWS * NCLASS) * 4;
        cudaFuncSetAttribute(head_kernel, cudaFuncAttributeMaxDynamicSharedMemorySize, head_smem);
    }

    cudaEventRecord(evFork, 0);
    cudaStreamWaitEvent(s1, evFork, 0);
    build_ell_kernel<<<N, 256, 0, s1>>>(adj);
    cudaEventRecord(evJoin, s1);

    prep_all_kernel<<<(N * NFEAT + 255) / 256, 256>>>(x, conv_w, w0);

    dim3 gg(NTILES, 4);
    gemm_hmma_kernel<<<gg, 128>>>(p_x16, N, NFEAT, p_B0img, nullptr, p_h016,
                                  b0, nullptr, 0.f, 0.f, 0);

    cudaStreamWaitEvent(0, evJoin, 0);

    const __half* hcur = p_h016;
    for (int l = 0; l < NLAYERS; l++) {
        float theta = logf(0.5f / (float)(l + 1) + 1.0f);
        float rtheta = 1.0f - theta;
        spmm_support_kernel<<<N / 2, 256>>>((const uint2*)hcur, (const uint2*)p_h016,
                                            (uint2*)p_sup16);
        int last = (l == NLAYERS - 1);
        gemm_hmma_kernel<<<gg, 128>>>(p_sup16, N, NHID,
                                      p_Bimg + (size_t)l * 65536,
                                      last ? p_h : nullptr,
                                      last ? nullptr : p_h16,
                                      nullptr, p_sup16, theta, rtheta, 1);
        hcur = p_h16;
    }

    head_kernel<<<(N + HROWS - 1) / HROWS, 128, head_smem>>>(p_h, w1, b1, out);
}